// round 1
// baseline (speedup 1.0000x reference)
#include <cuda_runtime.h>
#include <math.h>

#define B_   128
#define T_   512
#define D_   256
#define H_   512
#define G4_  2048   // 4*H

// ---- static device scratch (no cudaMalloc allowed) ----
__device__ float g_xp[(size_t)T_ * B_ * G4_];   // [T*B, 4H] precomputed input projections (+biases)
__device__ float g_h[2][B_ * H_];               // ping-pong hidden state
__device__ unsigned g_count = 0;                // grid barrier counter (returns to 0 every barrier)
__device__ volatile unsigned g_gen = 0;         // grid barrier generation (wraps to 0 at kernel end)

// =====================================================================
// Kernel 1: x_proj GEMM.  out[t*B+b, g] = sum_d x[b,t,d]*W_ih[g,d] + b_ih[g] + b_hh[g]
// Tiles: 128(M) x 64(N), K-chunks of 16, 256 threads, 8x4 microtile.
// =====================================================================
__global__ void __launch_bounds__(256) xproj_kernel(
    const float* __restrict__ x,     // [B*T, D] flat
    const float* __restrict__ Wih,   // [4H, D]
    const float* __restrict__ bih,   // [4H]
    const float* __restrict__ bhh)   // [4H]
{
    __shared__ float Ash[16][128];   // [k][m]
    __shared__ float Bsh[16][64];    // [k][n]

    const int mt = blockIdx.x >> 5;       // 512 M-tiles
    const int nt = blockIdx.x & 31;       // 32 N-tiles
    const int m0 = mt * 128;
    const int n0 = nt * 64;
    const int tid = threadIdx.x;
    const int tr = tid >> 4;              // 0..15 -> 8 rows each
    const int tc = tid & 15;              // 0..15 -> 4 cols each

    float acc[8][4];
#pragma unroll
    for (int r = 0; r < 8; ++r)
#pragma unroll
        for (int c = 0; c < 4; ++c) acc[r][c] = 0.f;

    for (int k0 = 0; k0 < D_; k0 += 16) {
        __syncthreads();
        // stage A: 128 rows x 16 k  (2 float4 per thread, transposed into Ash)
#pragma unroll
        for (int i = 0; i < 2; ++i) {
            int idx = tid + i * 256;
            int r  = idx >> 2;            // 0..127
            int kq = (idx & 3) * 4;       // 0,4,8,12
            float4 v = *(const float4*)(x + (size_t)(m0 + r) * D_ + k0 + kq);
            Ash[kq + 0][r] = v.x; Ash[kq + 1][r] = v.y;
            Ash[kq + 2][r] = v.z; Ash[kq + 3][r] = v.w;
        }
        // stage B: 64 rows(n) x 16 k  (1 float4 per thread, transposed)
        {
            int n  = tid >> 2;            // 0..63
            int kq = (tid & 3) * 4;
            float4 v = *(const float4*)(Wih + (size_t)(n0 + n) * D_ + k0 + kq);
            Bsh[kq + 0][n] = v.x; Bsh[kq + 1][n] = v.y;
            Bsh[kq + 2][n] = v.z; Bsh[kq + 3][n] = v.w;
        }
        __syncthreads();
#pragma unroll
        for (int k = 0; k < 16; ++k) {
            float4 a0 = *(const float4*)&Ash[k][tr * 8];
            float4 a1 = *(const float4*)&Ash[k][tr * 8 + 4];
            float4 b  = *(const float4*)&Bsh[k][tc * 4];
            float av[8] = {a0.x, a0.y, a0.z, a0.w, a1.x, a1.y, a1.z, a1.w};
#pragma unroll
            for (int r = 0; r < 8; ++r) {
                acc[r][0] += av[r] * b.x;
                acc[r][1] += av[r] * b.y;
                acc[r][2] += av[r] * b.z;
                acc[r][3] += av[r] * b.w;
            }
        }
    }

    // epilogue: add biases, remap row b*T+t -> t*B+b, write float4
    float4 bias;
    {
        int n = n0 + tc * 4;
        bias.x = bih[n + 0] + bhh[n + 0];
        bias.y = bih[n + 1] + bhh[n + 1];
        bias.z = bih[n + 2] + bhh[n + 2];
        bias.w = bih[n + 3] + bhh[n + 3];
    }
#pragma unroll
    for (int r = 0; r < 8; ++r) {
        int gr = m0 + tr * 8 + r;       // flat x row = b*T + t
        int b  = gr >> 9;               // / 512
        int t  = gr & 511;
        size_t orow = (size_t)t * B_ + b;
        float4 o;
        o.x = acc[r][0] + bias.x; o.y = acc[r][1] + bias.y;
        o.z = acc[r][2] + bias.z; o.w = acc[r][3] + bias.w;
        *(float4*)(g_xp + orow * G4_ + n0 + tc * 4) = o;
    }
}

// =====================================================================
// Kernel 2: persistent recurrent kernel. 128 CTAs (4 b-tiles x 32 j-tiles),
// one grid barrier per timestep. W_hh slice cached in SMEM for all steps.
// c kept in registers. Fused GEMM + LSTM cell.
// =====================================================================
__device__ __forceinline__ void grid_barrier(int step, int ncta)
{
    __syncthreads();
    if (threadIdx.x == 0) {
        unsigned next = (unsigned)((step + 1) & (T_ - 1));  // wraps to 0 after last step
        __threadfence();
        unsigned old = atomicAdd(&g_count, 1u);
        if (old == (unsigned)(ncta - 1)) {
            g_count = 0;          // reset before releasing (ordered by fence below)
            __threadfence();
            g_gen = next;
        } else {
            while (g_gen != next) { }
        }
        __threadfence();
    }
    __syncthreads();
}

__global__ void __launch_bounds__(256) lstm_rec_kernel(
    const float* __restrict__ Whh,   // [4H, H]
    float* __restrict__ out)         // [T*B, H]
{
    extern __shared__ float smem[];
    float* Wsh = smem;                       // [512][64]  k-major, col c = q*16 + jl
    float* Hsh = smem + 512 * 64;            // [32][512]  b-major
    float* Gsh = Hsh + 32 * 512;             // [32][68]   gates staging (padded rows)

    const int tid = threadIdx.x;
    const int bt = blockIdx.x >> 5;          // 0..3
    const int jt = blockIdx.x & 31;          // 0..31
    const int b0 = bt * 32;
    const int j0 = jt * 16;

    // --- one-time: load W_hh slice (64 gate-cols x 512 k) transposed into Wsh ---
    {
        int c  = tid >> 2;                   // 0..63
        int kq = (tid & 3) * 128;
        int q  = c >> 4;
        int jl = c & 15;
        const float* wrow = Whh + (size_t)(q * H_ + j0 + jl) * H_;
#pragma unroll 8
        for (int i = 0; i < 128; i += 4) {
            float4 v = *(const float4*)(wrow + kq + i);
            Wsh[(kq + i + 0) * 64 + c] = v.x;
            Wsh[(kq + i + 1) * 64 + c] = v.y;
            Wsh[(kq + i + 2) * 64 + c] = v.z;
            Wsh[(kq + i + 3) * 64 + c] = v.w;
        }
    }

    // GEMM thread mapping: 2 b-rows x 4 cols per thread
    const int tr  = tid >> 4;                // 0..15 -> rows 2tr, 2tr+1
    const int tc  = tid & 15;                // cols 4tc..4tc+3 (single gate q = tc/4)
    const int q   = tc >> 2;
    const int jl4 = (tc & 3) * 4;

    // elementwise ownership: elements e = 2*tid, 2*tid+1 -> (b = tid/8, j = (2*tid)&15)
    const int eb = tid >> 3;
    const int ej = (tid * 2) & 15;
    float c_reg[2] = {0.f, 0.f};

    for (int t = 0; t < T_; ++t) {
        // init accumulators from precomputed x-projection (includes both biases)
        float acc[2][4];
        {
            const float* xp = g_xp + ((size_t)t * B_ + b0) * G4_ + q * H_ + j0 + jl4;
#pragma unroll
            for (int r = 0; r < 2; ++r) {
                float4 v = *(const float4*)(xp + (size_t)(2 * tr + r) * G4_);
                acc[r][0] = v.x; acc[r][1] = v.y; acc[r][2] = v.z; acc[r][3] = v.w;
            }
        }

        if (t > 0) {
            // stage h_prev tile [32 x 512] (L2-coherent loads: written by other CTAs)
            {
                int hb = tid >> 3;               // 0..31
                int hk = (tid & 7) * 64;
                const float* src = g_h[(t - 1) & 1] + (size_t)(b0 + hb) * H_ + hk;
                float* dst = Hsh + hb * 512 + hk;
#pragma unroll
                for (int i = 0; i < 64; i += 4) {
                    float4 v = __ldcg((const float4*)(src + i));
                    *(float4*)(dst + i) = v;
                }
            }
            __syncthreads();
            // GEMM: acc += h_tile @ Wsh
            const float* hr0 = Hsh + (2 * tr) * 512;
            const float* hr1 = hr0 + 512;
            const float* wp  = Wsh + tc * 4;
#pragma unroll 8
            for (int k = 0; k < H_; ++k) {
                float4 w = *(const float4*)(wp + k * 64);
                float h0 = hr0[k];
                float h1 = hr1[k];
                acc[0][0] += h0 * w.x; acc[0][1] += h0 * w.y;
                acc[0][2] += h0 * w.z; acc[0][3] += h0 * w.w;
                acc[1][0] += h1 * w.x; acc[1][1] += h1 * w.y;
                acc[1][2] += h1 * w.z; acc[1][3] += h1 * w.w;
            }
        }

        // stage gates to SMEM so each thread can gather its (i,f,g,o) quadruple
#pragma unroll
        for (int r = 0; r < 2; ++r) {
            float* g = Gsh + (2 * tr + r) * 68 + tc * 4;
            g[0] = acc[r][0]; g[1] = acc[r][1]; g[2] = acc[r][2]; g[3] = acc[r][3];
        }
        __syncthreads();

        // fused LSTM cell: 2 elements per thread, c in registers
        float* hout = g_h[t & 1];
#pragma unroll
        for (int p = 0; p < 2; ++p) {
            int j = ej + p;
            const float* gr = Gsh + eb * 68;
            float gi = gr[0  + j];
            float gf = gr[16 + j];
            float gg = gr[32 + j];
            float go = gr[48 + j];
            float i_s = 1.f / (1.f + __expf(-gi));
            float f_s = 1.f / (1.f + __expf(-gf));
            float g_t = tanhf(gg);
            float o_s = 1.f / (1.f + __expf(-go));
            float cv  = f_s * c_reg[p] + i_s * g_t;
            c_reg[p]  = cv;
            float hv  = o_s * tanhf(cv);
            int gb = b0 + eb;
            int gj = j0 + j;
            hout[(size_t)gb * H_ + gj] = hv;
            out[((size_t)t * B_ + gb) * H_ + gj] = hv;
        }

        grid_barrier(t, gridDim.x);   // releases writes of h_t; barrier state wraps to 0 at t=511
    }
}

// =====================================================================
extern "C" void kernel_launch(void* const* d_in, const int* in_sizes, int n_in,
                              void* d_out, int out_size)
{
    const float* x   = (const float*)d_in[0];   // [B,T,D]
    const float* Wih = (const float*)d_in[1];   // [4H,D]
    const float* Whh = (const float*)d_in[2];   // [4H,H]
    const float* bih = (const float*)d_in[3];   // [4H]
    const float* bhh = (const float*)d_in[4];   // [4H]
    float* out = (float*)d_out;

    // Phase 1: input projections for all timesteps
    xproj_kernel<<<16384, 256>>>(x, Wih, bih, bhh);

    // Phase 2: persistent recurrence (128 CTAs, ~200.5 KB dynamic SMEM each)
    size_t smem2 = (size_t)(512 * 64 + 32 * 512 + 32 * 68) * sizeof(float);
    cudaFuncSetAttribute(lstm_rec_kernel,
                         cudaFuncAttributeMaxDynamicSharedMemorySize, (int)smem2);
    lstm_rec_kernel<<<128, 256, smem2>>>(Whh, out);
}

// round 3
// speedup vs baseline: 4.2119x; 4.2119x over previous
#include <cuda_runtime.h>
#include <math.h>
#include <cstdint>

#define B_   128
#define T_   512
#define D_   256
#define H_   512
#define G4_  2048   // 4*H

// ---- static device scratch (no cudaMalloc allowed) ----
__device__ float g_xp[(size_t)T_ * B_ * G4_];   // [T*B, 4H] x-projections (+biases)
__device__ float g_h[2][B_ * H_];               // ping-pong hidden state (tf32-rounded)
__device__ unsigned g_count = 0;
__device__ volatile unsigned g_gen = 0;

// =====================================================================
// helpers
// =====================================================================
__device__ __forceinline__ float tf32r(float x) {
    float y; asm("cvt.rna.tf32.f32 %0, %1;" : "=f"(y) : "f"(x)); return y;
}

// mma.sync m16n8k8 tf32, fp32 accum (generic PTX, runs on HMMA pipe)
__device__ __forceinline__ void mma1688(float* c, const uint32_t* a, const uint32_t* b) {
    asm volatile(
        "mma.sync.aligned.m16n8k8.row.col.f32.tf32.tf32.f32 "
        "{%0,%1,%2,%3}, {%4,%5,%6,%7}, {%8,%9}, {%0,%1,%2,%3};"
        : "+f"(c[0]), "+f"(c[1]), "+f"(c[2]), "+f"(c[3])
        : "r"(a[0]), "r"(a[1]), "r"(a[2]), "r"(a[3]), "r"(b[0]), "r"(b[1]));
}

__device__ __forceinline__ void grid_barrier(int step, unsigned ncta)
{
    __syncthreads();
    if (threadIdx.x == 0) {
        unsigned next = (unsigned)((step + 1) & (T_ - 1));
        __threadfence();
        unsigned old = atomicAdd(&g_count, 1u);
        if (old == ncta - 1u) {
            g_count = 0;
            __threadfence();
            g_gen = next;
        } else {
            while (g_gen != next) { }
        }
        __threadfence();
    }
    __syncthreads();
}

// =====================================================================
// Kernel 1: x_proj GEMM via tf32 mma.
//   grid = 512 m-tiles x 32 n-tiles; CTA tile M=128, N=64, K=256 (4 chunks of 64)
//   8 warps, each warp tile M=32 x N=32 (2 A-frags x 4 B-frags)
// =====================================================================
#define XA_STR 68      // A smem row stride (floats), pad 4
#define XB_STR 68
#define XP_SMEM ((128 * XA_STR + 64 * XB_STR) * 4)

__global__ void __launch_bounds__(256, 1) xproj_mma(
    const float* __restrict__ x,     // [B*T, D]
    const float* __restrict__ Wih,   // [4H, D]
    const float* __restrict__ bih,
    const float* __restrict__ bhh)
{
    extern __shared__ float sm[];
    float* Ash = sm;                   // [128][68]
    float* Bsh = sm + 128 * XA_STR;    // [64][68]

    const int tid  = threadIdx.x;
    const int wid  = tid >> 5;
    const int lane = tid & 31;
    const int g    = lane >> 2;        // 0..7
    const int tig  = lane & 3;         // 0..3
    const int wm   = wid & 3;          // M warp 0..3 (rows wm*32)
    const int wn   = wid >> 1 & 2;     // unused placeholder
    const int wcol = (wid >> 2) * 32;  // N warp col base: 0 or 32

    const int mt = blockIdx.x >> 5;
    const int nt = blockIdx.x & 31;
    const int m0 = mt * 128;
    const int n0 = nt * 64;
    (void)wn;

    float c[2][4][4];
#pragma unroll
    for (int a = 0; a < 2; ++a)
#pragma unroll
        for (int b = 0; b < 4; ++b)
#pragma unroll
            for (int i = 0; i < 4; ++i) c[a][b][i] = 0.f;

    for (int kc = 0; kc < 4; ++kc) {
        const int k0 = kc * 64;
        __syncthreads();
        // stage A chunk: 128 rows x 64 k (tf32-rounded)
        {
            int row = tid >> 1;
            int h   = (tid & 1) * 32;
            const float* src = x + (size_t)(m0 + row) * D_ + k0 + h;
            float* dst = Ash + row * XA_STR + h;
#pragma unroll
            for (int i = 0; i < 8; ++i) {
                float4 v = *(const float4*)(src + i * 4);
                v.x = tf32r(v.x); v.y = tf32r(v.y); v.z = tf32r(v.z); v.w = tf32r(v.w);
                *(float4*)(dst + i * 4) = v;
            }
        }
        // stage B chunk: 64 n x 64 k
        {
            int n = tid >> 2;
            int h = (tid & 3) * 16;
            const float* src = Wih + (size_t)(n0 + n) * D_ + k0 + h;
            float* dst = Bsh + n * XB_STR + h;
#pragma unroll
            for (int i = 0; i < 4; ++i) {
                float4 v = *(const float4*)(src + i * 4);
                v.x = tf32r(v.x); v.y = tf32r(v.y); v.z = tf32r(v.z); v.w = tf32r(v.w);
                *(float4*)(dst + i * 4) = v;
            }
        }
        __syncthreads();

        const float* a0p = Ash + (wm * 32 + g) * XA_STR;
        const float* a1p = Ash + (wm * 32 + g + 8) * XA_STR;
        const float* a2p = Ash + (wm * 32 + 16 + g) * XA_STR;
        const float* a3p = Ash + (wm * 32 + 24 + g) * XA_STR;
        const float* bp0 = Bsh + (wcol + 0  + g) * XB_STR;
        const float* bp1 = Bsh + (wcol + 8  + g) * XB_STR;
        const float* bp2 = Bsh + (wcol + 16 + g) * XB_STR;
        const float* bp3 = Bsh + (wcol + 24 + g) * XB_STR;

#pragma unroll 4
        for (int kk = 0; kk < 8; ++kk) {
            const int k8 = kk * 8 + tig;
            uint32_t af0[4] = { __float_as_uint(a0p[k8]), __float_as_uint(a1p[k8]),
                                __float_as_uint(a0p[k8 + 4]), __float_as_uint(a1p[k8 + 4]) };
            uint32_t af1[4] = { __float_as_uint(a2p[k8]), __float_as_uint(a3p[k8]),
                                __float_as_uint(a2p[k8 + 4]), __float_as_uint(a3p[k8 + 4]) };
            uint32_t bf0[2] = { __float_as_uint(bp0[k8]), __float_as_uint(bp0[k8 + 4]) };
            uint32_t bf1[2] = { __float_as_uint(bp1[k8]), __float_as_uint(bp1[k8 + 4]) };
            uint32_t bf2[2] = { __float_as_uint(bp2[k8]), __float_as_uint(bp2[k8 + 4]) };
            uint32_t bf3[2] = { __float_as_uint(bp3[k8]), __float_as_uint(bp3[k8 + 4]) };
            mma1688(c[0][0], af0, bf0); mma1688(c[0][1], af0, bf1);
            mma1688(c[0][2], af0, bf2); mma1688(c[0][3], af0, bf3);
            mma1688(c[1][0], af1, bf0); mma1688(c[1][1], af1, bf1);
            mma1688(c[1][2], af1, bf2); mma1688(c[1][3], af1, bf3);
        }
    }

    // epilogue: bias add + remap row (b*T+t -> t*B+b), float2 stores
    float2 bias[4];
#pragma unroll
    for (int nf = 0; nf < 4; ++nf) {
        int col = n0 + wcol + nf * 8 + 2 * tig;
        bias[nf].x = bih[col] + bhh[col];
        bias[nf].y = bih[col + 1] + bhh[col + 1];
    }
#pragma unroll
    for (int mf = 0; mf < 2; ++mf) {
#pragma unroll
        for (int rs = 0; rs < 2; ++rs) {
            int grow = m0 + wm * 32 + mf * 16 + g + rs * 8;
            int b = grow >> 9;         // / T_
            int t = grow & 511;
            float* orow = g_xp + ((size_t)t * B_ + b) * G4_ + n0 + wcol + 2 * tig;
#pragma unroll
            for (int nf = 0; nf < 4; ++nf) {
                float2 v;
                v.x = c[mf][nf][rs * 2 + 0] + bias[nf].x;
                v.y = c[mf][nf][rs * 2 + 1] + bias[nf].y;
                *(float2*)(orow + nf * 8) = v;
            }
        }
    }
}

// =====================================================================
// Kernel 2: persistent tf32 mma recurrence.
//   128 CTAs = 4 b-tiles x 32 j-tiles; CTA tile M=32(batch), N=64(4 gates x 16), K=512
//   256 threads; warps 0-3 compute (warp tile M=32 x N=16); all warps stage/cell
// =====================================================================
#define W_STR 516           // Wsh/Hsh row stride (floats), pad 4
#define G_STR 68
#define REC_SMEM ((64 * W_STR + 32 * W_STR + 32 * G_STR) * 4)

__global__ void __launch_bounds__(256, 1) lstm_rec_mma(
    const float* __restrict__ Whh,   // [4H, H]
    float* __restrict__ out)         // [T*B, H]
{
    extern __shared__ float sm[];
    float* Wsh = sm;                     // [64 n][516]
    float* Hsh = sm + 64 * W_STR;        // [32 b][516]
    float* Gsh = Hsh + 32 * W_STR;       // [32 b][68]

    const int tid  = threadIdx.x;
    const int wid  = tid >> 5;
    const int lane = tid & 31;
    const int g    = lane >> 2;
    const int tig  = lane & 3;

    const int bt = blockIdx.x >> 5;
    const int jt = blockIdx.x & 31;
    const int b0 = bt * 32;
    const int j0 = jt * 16;

    // ---- one-time: W_hh slice [64 n][512 k] -> SMEM (tf32-rna) ----
    {
        int n  = tid >> 2;               // 0..63 : n = q*16 + jl
        int kq = (tid & 3) * 128;
        int q  = n >> 4, jl = n & 15;
        const float* wr = Whh + (size_t)(q * H_ + j0 + jl) * H_ + kq;
        float* dst = Wsh + n * W_STR + kq;
#pragma unroll 8
        for (int i = 0; i < 128; i += 4) {
            float4 v = *(const float4*)(wr + i);
            v.x = tf32r(v.x); v.y = tf32r(v.y); v.z = tf32r(v.z); v.w = tf32r(v.w);
            *(float4*)(dst + i) = v;
        }
    }
    __syncthreads();

    // compute-warp constants (warps 0-3); warp w owns gate q=w, cols wn0..wn0+15
    const int wn0 = wid * 16;

    // cell state: thread owns (b = tid>>3, j = (tid&7)*2 .. +1)
    const int cb = tid >> 3;
    const int cj = (tid & 7) * 2;
    float c_reg[2] = {0.f, 0.f};

    // accumulators + xp prefetch (warps 0-3 only meaningful)
    float c[2][2][4];
    float pf[2][2][4];

    // prefetch xp for t=0
    if (wid < 4) {
        const float* xb = g_xp + ((size_t)0 * B_ + b0) * G4_ + wn0 * 32 /*w*512*/ + j0 + 2 * tig;
        // note: wn0*32 == wid*512
#pragma unroll
        for (int mf = 0; mf < 2; ++mf)
#pragma unroll
            for (int rs = 0; rs < 2; ++rs) {
                const float* r = xb + (size_t)(mf * 16 + g + rs * 8) * G4_;
#pragma unroll
                for (int nf = 0; nf < 2; ++nf) {
                    float2 v = *(const float2*)(r + nf * 8);
                    pf[mf][nf][rs * 2 + 0] = v.x;
                    pf[mf][nf][rs * 2 + 1] = v.y;
                }
            }
    }

    for (int t = 0; t < T_; ++t) {
        if (wid < 4) {
#pragma unroll
            for (int mf = 0; mf < 2; ++mf)
#pragma unroll
                for (int nf = 0; nf < 2; ++nf)
#pragma unroll
                    for (int i = 0; i < 4; ++i) c[mf][nf][i] = pf[mf][nf][i];
        }

        if (t > 0) {
            // stage h_{t-1}: [32 b][512], L2-coherent loads
            {
                int row = tid >> 3;
                int s   = (tid & 7) * 4;
                const float* src = g_h[(t - 1) & 1] + (size_t)(b0 + row) * H_ + s;
                float* dst = Hsh + row * W_STR + s;
#pragma unroll
                for (int i = 0; i < 16; ++i) {
                    float4 v = __ldcg((const float4*)(src + i * 32));
                    *(float4*)(dst + i * 32) = v;
                }
            }
            __syncthreads();

            if (wid < 4) {
                const float* h0p = Hsh + g * W_STR;
                const float* h1p = Hsh + (g + 8) * W_STR;
                const float* h2p = Hsh + (16 + g) * W_STR;
                const float* h3p = Hsh + (24 + g) * W_STR;
                const float* w0p = Wsh + (wn0 + g) * W_STR;
                const float* w1p = Wsh + (wn0 + 8 + g) * W_STR;
#pragma unroll 4
                for (int kk = 0; kk < 64; ++kk) {
                    const int k8 = kk * 8 + tig;
                    uint32_t af0[4] = { __float_as_uint(h0p[k8]), __float_as_uint(h1p[k8]),
                                        __float_as_uint(h0p[k8 + 4]), __float_as_uint(h1p[k8 + 4]) };
                    uint32_t af1[4] = { __float_as_uint(h2p[k8]), __float_as_uint(h3p[k8]),
                                        __float_as_uint(h2p[k8 + 4]), __float_as_uint(h3p[k8 + 4]) };
                    uint32_t bf0[2] = { __float_as_uint(w0p[k8]), __float_as_uint(w0p[k8 + 4]) };
                    uint32_t bf1[2] = { __float_as_uint(w1p[k8]), __float_as_uint(w1p[k8 + 4]) };
                    mma1688(c[0][0], af0, bf0); mma1688(c[0][1], af0, bf1);
                    mma1688(c[1][0], af1, bf0); mma1688(c[1][1], af1, bf1);
                }
            }
        }

        // stage gates to SMEM
        if (wid < 4) {
#pragma unroll
            for (int mf = 0; mf < 2; ++mf)
#pragma unroll
                for (int rs = 0; rs < 2; ++rs) {
                    float* gr = Gsh + (mf * 16 + g + rs * 8) * G_STR + wn0 + 2 * tig;
#pragma unroll
                    for (int nf = 0; nf < 2; ++nf) {
                        float2 v;
                        v.x = c[mf][nf][rs * 2 + 0];
                        v.y = c[mf][nf][rs * 2 + 1];
                        *(float2*)(gr + nf * 8) = v;
                    }
                }
        }
        __syncthreads();

        // prefetch xp for t+1 (independent of this step's cell)
        if (wid < 4 && t + 1 < T_) {
            const float* xb = g_xp + ((size_t)(t + 1) * B_ + b0) * G4_ + wid * 512 + j0 + 2 * tig;
#pragma unroll
            for (int mf = 0; mf < 2; ++mf)
#pragma unroll
                for (int rs = 0; rs < 2; ++rs) {
                    const float* r = xb + (size_t)(mf * 16 + g + rs * 8) * G4_;
#pragma unroll
                    for (int nf = 0; nf < 2; ++nf) {
                        float2 v = *(const float2*)(r + nf * 8);
                        pf[mf][nf][rs * 2 + 0] = v.x;
                        pf[mf][nf][rs * 2 + 1] = v.y;
                    }
                }
        }

        // fused LSTM cell: 2 elements per thread, c in registers
        {
            const float* gr = Gsh + cb * G_STR;
            float h2[2];
#pragma unroll
            for (int p = 0; p < 2; ++p) {
                int j = cj + p;
                float gi = gr[0  + j];
                float gf = gr[16 + j];
                float gg = gr[32 + j];
                float go = gr[48 + j];
                float i_s = 1.f / (1.f + __expf(-gi));
                float f_s = 1.f / (1.f + __expf(-gf));
                float o_s = 1.f / (1.f + __expf(-go));
                float g_t = tanhf(gg);
                float cv  = f_s * c_reg[p] + i_s * g_t;
                c_reg[p]  = cv;
                h2[p]     = o_s * tanhf(cv);
            }
            float* op = out + ((size_t)t * B_ + b0 + cb) * H_ + j0 + cj;
            float2 ov; ov.x = h2[0]; ov.y = h2[1];
            *(float2*)op = ov;
            float* hp = g_h[t & 1] + (size_t)(b0 + cb) * H_ + j0 + cj;
            float2 hv; hv.x = tf32r(h2[0]); hv.y = tf32r(h2[1]);
            *(float2*)hp = hv;
        }

        grid_barrier(t, 128u);
    }
}

// =====================================================================
extern "C" void kernel_launch(void* const* d_in, const int* in_sizes, int n_in,
                              void* d_out, int out_size)
{
    const float* x   = (const float*)d_in[0];   // [B,T,D]
    const float* Wih = (const float*)d_in[1];   // [4H,D]
    const float* Whh = (const float*)d_in[2];   // [4H,H]
    const float* bih = (const float*)d_in[3];   // [4H]
    const float* bhh = (const float*)d_in[4];   // [4H]
    float* out = (float*)d_out;

    cudaFuncSetAttribute(xproj_mma,
                         cudaFuncAttributeMaxDynamicSharedMemorySize, XP_SMEM);
    xproj_mma<<<16384, 256, XP_SMEM>>>(x, Wih, bih, bhh);

    cudaFuncSetAttribute(lstm_rec_mma,
                         cudaFuncAttributeMaxDynamicSharedMemorySize, REC_SMEM);
    lstm_rec_mma<<<128, 256, REC_SMEM>>>(Whh, out);
}